// round 6
// baseline (speedup 1.0000x reference)
#include <cuda_runtime.h>
#include <cstdint>

#define NROWS 8000
#define NDIM  9
#define NBLK  148            // one block per SM, wave-1 co-resident
#define NTHR  1024
#define RPT   8              // rows per thread in scan (1024*8 = 8192 >= 8000)
#define N4    (NROWS / 4)    // 2000 float4 per row
#define GROWS 2              // rows per staging buffer / per group
#define NBUF  3              // staging buffers (triple buffer)
#define NGRP  (NROWS / GROWS)                         // 4000 groups
#define ROW_BYTES (NROWS * 4)                         // 32000 B per output row
#define STAGE_FLOATS (GROWS * NROWS)                  // 16000 floats per buffer
#define SMEM_FLOATS (NROWS + NBUF * STAGE_FLOATS)     // 56000 floats
#define SMEM_BYTES  (SMEM_FLOATS * 4)                 // 224000 B

// Scratch (device globals — no allocation allowed in kernel_launch)
__device__ unsigned long long g_bar = 0ULL;   // monotonic grid barrier counter
__device__ __align__(16) float g_s1[NROWS];
__device__ __align__(16) float g_s2[NROWS];
__device__ __align__(16) float g_f1[NROWS];
__device__ __align__(16) float g_f2[NROWS];

__device__ __forceinline__ uint32_t smem_u32(const void* p) {
    uint32_t a;
    asm("{ .reg .u64 t; cvta.to.shared.u64 t, %1; cvt.u32.u64 %0, t; }"
        : "=r"(a) : "l"(p));
    return a;
}

__global__ __launch_bounds__(NTHR, 1)
void anfis_fused_kernel(const float* __restrict__ x,
                        const float* __restrict__ a1, const float* __restrict__ c1,
                        const float* __restrict__ a2, const float* __restrict__ c2,
                        const float* __restrict__ w_fc1, const float* __restrict__ b_fc1,
                        const float* __restrict__ w_fc2, const float* __restrict__ b_fc2,
                        float* __restrict__ out)
{
    extern __shared__ float smem[];
    float* sw1   = smem;             // [NROWS] w1_bar
    float* stage = smem + NROWS;     // [NBUF][GROWS*NROWS]
    __shared__ float2 sh[32];

    const int tid  = threadIdx.x;
    const int lane = tid & 31;
    const int warp = tid >> 5;

    // ---------------- Phase A: per-row sums + fc outputs (grid-parallel) ----
    {
        const int row = blockIdx.x * NTHR + tid;
        if (row < NROWS) {
            const float ia1 = 1.0f / a1[0], cc1 = c1[0];
            const float ia2 = 1.0f / a2[0], cc2 = c2[0];
            float acc1 = 0.0f, acc2 = 0.0f;
            float ff1 = b_fc1[0], ff2 = b_fc2[0];
#pragma unroll
            for (int d = 0; d < NDIM; d++) {
                const float xv = __ldg(&x[row * NDIM + d]);
                const float t1 = (xv - cc1) * ia1;
                const float t2 = (xv - cc2) * ia2;
                acc1 = fmaf(t1, t1, acc1);
                acc2 = fmaf(t2, t2, acc2);
                ff1  = fmaf(xv, __ldg(&w_fc1[d]), ff1);
                ff2  = fmaf(xv, __ldg(&w_fc2[d]), ff2);
            }
            g_s1[row] = acc1;
            g_s2[row] = acc2;
            g_f1[row] = ff1;
            g_f2[row] = ff2;
        }
    }

    // ---------------- Grid barrier (monotonic counter, replay-safe) ---------
    __syncthreads();
    if (tid == 0) {
        __threadfence();
        const unsigned long long my = atomicAdd(&g_bar, 1ULL) + 1ULL;
        const unsigned long long target = ((my + (NBLK - 1ULL)) / NBLK) * NBLK;
        volatile unsigned long long* p = &g_bar;
        while (*p < target) { }
        __threadfence();
    }
    __syncthreads();

    // ---------------- Phase B: redundant scan -> w1_bar into smem -----------
    {
        const int base = tid * RPT;
        float ls1[RPT], ls2[RPT];
        float run1 = 0.0f, run2 = 0.0f;
#pragma unroll
        for (int r = 0; r < RPT; r++) {
            const int row = base + r;
            if (row < NROWS) {
                run1 += g_s1[row];
                run2 += g_s2[row];
            }
            ls1[r] = run1;
            ls2[r] = run2;
        }

        float inc1 = run1, inc2 = run2;
#pragma unroll
        for (int o = 1; o < 32; o <<= 1) {
            const float n1 = __shfl_up_sync(0xffffffffu, inc1, o);
            const float n2 = __shfl_up_sync(0xffffffffu, inc2, o);
            if (lane >= o) { inc1 += n1; inc2 += n2; }
        }
        if (lane == 31) sh[warp] = make_float2(inc1, inc2);
        __syncthreads();
        if (warp == 0) {
            const float2 v = sh[lane];
            float a = v.x, b = v.y;
#pragma unroll
            for (int o = 1; o < 32; o <<= 1) {
                const float n1 = __shfl_up_sync(0xffffffffu, a, o);
                const float n2 = __shfl_up_sync(0xffffffffu, b, o);
                if (lane >= o) { a += n1; b += n2; }
            }
            sh[lane] = make_float2(a - v.x, b - v.y);  // exclusive prefix
        }
        __syncthreads();

        const float ex1 = sh[warp].x + (inc1 - run1);
        const float ex2 = sh[warp].y + (inc2 - run2);

#pragma unroll
        for (int r = 0; r < RPT; r++) {
            const int row = base + r;
            if (row < NROWS) {
                const float w1v = expf(-(ex1 + ls1[r]));
                const float w2v = expf(-(ex2 + ls2[r]));
                sw1[row] = w1v / (w1v + w2v);   // w1_bar; w2_bar = 1 - w1_bar
            }
        }
    }
    __syncthreads();

    // ---------------- Phase C: compute into smem, TMA bulk-store to GMEM ----
    {
        const float4* w4 = reinterpret_cast<const float4*>(sw1);
        const uint32_t stage_u32 = smem_u32(stage);
        int it = 0;

        for (int g = blockIdx.x; g < NGRP; g += NBLK, ++it) {
            const int buf = it % NBUF;

            // Reuse gate: at most NBUF-1 bulk groups pending -> this buffer's
            // smem reads are complete.
            if (it >= NBUF && tid == 0)
                asm volatile("cp.async.bulk.wait_group.read %0;" :: "n"(NBUF - 1) : "memory");
            __syncthreads();

            const int i0 = g * GROWS;
            const float f2_0 = g_f2[i0],     d0 = g_f1[i0]     - f2_0;
            const float f2_1 = g_f2[i0 + 1], d1 = g_f1[i0 + 1] - f2_1;

            float4* sb4 = reinterpret_cast<float4*>(stage + buf * STAGE_FLOATS);
            for (int j = tid; j < N4; j += NTHR) {
                const float4 a = w4[j];
                float4 o0, o1;
                o0.x = fmaf(d0, a.x, f2_0);
                o0.y = fmaf(d0, a.y, f2_0);
                o0.z = fmaf(d0, a.z, f2_0);
                o0.w = fmaf(d0, a.w, f2_0);
                o1.x = fmaf(d1, a.x, f2_1);
                o1.y = fmaf(d1, a.y, f2_1);
                o1.z = fmaf(d1, a.z, f2_1);
                o1.w = fmaf(d1, a.w, f2_1);
                sb4[j]      = o0;
                sb4[N4 + j] = o1;
            }

            // Order generic-proxy STS before async-proxy TMA reads.
            asm volatile("fence.proxy.async.shared::cta;" ::: "memory");
            __syncthreads();

            if (tid == 0) {
                const float* gdst = out + (size_t)i0 * NROWS;
                const uint32_t ssrc = stage_u32 + (uint32_t)(buf * STAGE_FLOATS * 4);
                asm volatile(
                    "cp.async.bulk.global.shared::cta.bulk_group [%0], [%1], %2;"
                    :: "l"(gdst), "r"(ssrc), "n"(GROWS * ROW_BYTES) : "memory");
                asm volatile("cp.async.bulk.commit_group;" ::: "memory");
            }
        }

        // Drain all outstanding bulk stores before CTA exit.
        if (tid == 0)
            asm volatile("cp.async.bulk.wait_group %0;" :: "n"(0) : "memory");
    }
}

// ---------------------------------------------------------------------------
extern "C" void kernel_launch(void* const* d_in, const int* in_sizes, int n_in,
                              void* d_out, int out_size)
{
    const float* x     = (const float*)d_in[0];
    const float* a1    = (const float*)d_in[1];
    const float* c1    = (const float*)d_in[2];
    const float* a2    = (const float*)d_in[3];
    const float* c2    = (const float*)d_in[4];
    const float* w_fc1 = (const float*)d_in[5];
    const float* b_fc1 = (const float*)d_in[6];
    const float* w_fc2 = (const float*)d_in[7];
    const float* b_fc2 = (const float*)d_in[8];
    float* out = (float*)d_out;

    cudaFuncSetAttribute(anfis_fused_kernel,
                         cudaFuncAttributeMaxDynamicSharedMemorySize, SMEM_BYTES);
    anfis_fused_kernel<<<NBLK, NTHR, SMEM_BYTES>>>(x, a1, c1, a2, c2,
                                                   w_fc1, b_fc1, w_fc2, b_fc2, out);
}